// round 11
// baseline (speedup 1.0000x reference)
#include <cuda_runtime.h>
#include <math.h>

#define T_SEQ 2048
#define H_DIM 1024
#define IN_DIM 512
#define G4 4096
#define OUT_DIM 4
#define NCTA 128
#define SLICE 8            // hidden units per CTA (one per warp)

#define OFF_MEAN 0
#define OFF_LSTD (T_SEQ * OUT_DIM)
#define OFF_HT   (2 * T_SEQ * OUT_DIM)
#define OFF_CT   (2 * T_SEQ * OUT_DIM + H_DIM)

// ---------------- scratch (static device memory: no allocation) ----------------
__device__ float g_gx[T_SEQ * G4];     // 32 MB: x @ w_ih.T + b_ih + b_hh
__device__ float g_ys[T_SEQ * H_DIM];  // 8 MB: h trace (hot exchange + fc1 input)
__device__ float g_h1[T_SEQ * H_DIM];
__device__ float g_h2[T_SEQ * H_DIM];
__device__ unsigned g_ctr;             // single step counter (RED target)

__global__ void reset_kernel() {
    if (threadIdx.x == 0) g_ctr = 0u;
}

// ---------------- packed f32x2 helpers ----------------
__device__ __forceinline__ unsigned long long pk2(float a, float b) {
    unsigned long long r;
    asm("mov.b64 %0, {%1, %2};" : "=l"(r) : "f"(a), "f"(b));
    return r;
}
__device__ __forceinline__ void fma2(unsigned long long& d,
                                     unsigned long long a, unsigned long long b) {
    asm("fma.rn.f32x2 %0, %1, %2, %0;" : "+l"(d) : "l"(a), "l"(b));
}
__device__ __forceinline__ float lo2(unsigned long long v) {
    return __uint_as_float((unsigned)v);
}
__device__ __forceinline__ float hi2(unsigned long long v) {
    return __uint_as_float((unsigned)(v >> 32));
}
__device__ __forceinline__ float tanh_fast(float x) {
    float r;
    asm("tanh.approx.f32 %0, %1;" : "=f"(r) : "f"(x));
    return r;
}
// sigmoid(x) = 0.5 + 0.5*tanh(x/2): single MUFU instead of exp+rcp
__device__ __forceinline__ float sigmoid_fast(float x) {
    return fmaf(tanh_fast(0.5f * x), 0.5f, 0.5f);
}

// ---------------- tiled GEMM: C[M,N] = A[M,K] @ B[N,K]^T + b1 (+b2), opt relu ----
#define BM 64
#define BN 64
#define BK 16

__global__ __launch_bounds__(256) void gemm_nt_kernel(
    const float* __restrict__ A, const float* __restrict__ B,
    const float* __restrict__ b1, const float* __restrict__ b2,
    float* __restrict__ C, int M, int N, int K, int relu)
{
    __shared__ float As[BK][BM + 4];
    __shared__ float Bs[BK][BN + 4];

    const int bm = blockIdx.y * BM;
    const int bn = blockIdx.x * BN;
    const int tid = threadIdx.x;
    const int tx = tid & 15;
    const int ty = tid >> 4;

    const int lr = tid >> 2;
    const int lk = (tid & 3) * 4;

    unsigned long long acc2[4][2] = {};

    for (int k0 = 0; k0 < K; k0 += BK) {
        float4 av = *(const float4*)(A + (size_t)(bm + lr) * K + k0 + lk);
        float4 bv = *(const float4*)(B + (size_t)(bn + lr) * K + k0 + lk);
        __syncthreads();
        As[lk + 0][lr] = av.x; As[lk + 1][lr] = av.y;
        As[lk + 2][lr] = av.z; As[lk + 3][lr] = av.w;
        Bs[lk + 0][lr] = bv.x; Bs[lk + 1][lr] = bv.y;
        Bs[lk + 2][lr] = bv.z; Bs[lk + 3][lr] = bv.w;
        __syncthreads();

#pragma unroll
        for (int kk = 0; kk < BK; kk++) {
            const float4 a4 = *(const float4*)&As[kk][ty * 4];
            const float4 b4 = *(const float4*)&Bs[kk][tx * 4];
            const unsigned long long b01 = pk2(b4.x, b4.y);
            const unsigned long long b23 = pk2(b4.z, b4.w);
            const float a_[4] = {a4.x, a4.y, a4.z, a4.w};
#pragma unroll
            for (int i = 0; i < 4; i++) {
                const unsigned long long aii = pk2(a_[i], a_[i]);
                fma2(acc2[i][0], aii, b01);
                fma2(acc2[i][1], aii, b23);
            }
        }
    }

#pragma unroll
    for (int i = 0; i < 4; i++) {
        const int m = bm + ty * 4 + i;
        float cj[4] = {lo2(acc2[i][0]), hi2(acc2[i][0]),
                       lo2(acc2[i][1]), hi2(acc2[i][1])};
#pragma unroll
        for (int j = 0; j < 4; j++) {
            const int n = bn + tx * 4 + j;
            float v = cj[j] + b1[n];
            if (b2) v += b2[n];
            if (relu) v = fmaxf(v, 0.0f);
            C[(size_t)m * N + n] = v;
        }
    }
}

// ---------------- persistent LSTM recurrence ----------------
// 128 CTAs x 256 threads (8 warps). Warp w owns unit u = cta*8 + w (4 gate rows
// register-resident, f32x2). h(t-1) staged once per CTA into smem (1 float4 per
// thread), dot reads via LDS.128. Gates lane-parallel (lanes 0..3, tanh-only
// activations). Sync: single counter, release-RED by warp 7 lane 0, single
// acquire-poller (warp 7 lane 0).
__global__ __launch_bounds__(256, 1) void lstm_kernel(
    const float* __restrict__ w_hh,
    const float* __restrict__ h0, const float* __restrict__ c0,
    const float* __restrict__ gx,
    float* __restrict__ ys,
    float* __restrict__ out)
{
    const int cta = blockIdx.x;
    const int hs = cta * SLICE;
    const int tid = threadIdx.x;
    const int w = tid >> 5;              // warp 0..7; owns unit hs+w
    const int l = tid & 31;
    const int u = hs + w;                // this warp's hidden unit

    // Persistent weights: 4 gate rows of unit u, packed f32x2.
    unsigned long long wpk[4][16];
#pragma unroll
    for (int g = 0; g < 4; g++) {
        const float* wrow = w_hh + (size_t)(g * H_DIM + u) * H_DIM;
#pragma unroll
        for (int k4 = 0; k4 < 8; k4++) {
            const int base = 4 * l + 128 * k4;
            wpk[g][2 * k4 + 0] = pk2(wrow[base + 0], wrow[base + 1]);
            wpk[g][2 * k4 + 1] = pk2(wrow[base + 2], wrow[base + 3]);
        }
    }

    __shared__ float sh_h[H_DIM];

    // c state: lane 0 of each warp
    float creg = (l == 0) ? c0[u] : 0.0f;

    // gx prefetch for step 0: lanes 0..3 each hold their gate's input
    float gxv = 0.0f;
    if (l < 4) gxv = __ldcg(gx + l * H_DIM + u);

    unsigned* ctr = &g_ctr;

    for (int t = 0; t < T_SEQ; t++) {
        // ---- wait for h(t-1): single poller (warp 7 lane 0) ----
        if (t > 0) {
            if (tid == 7 * 32) {
                const unsigned tgt = (unsigned)(NCTA * t);
                unsigned v;
                int spins = 0;
                do {
                    asm volatile("ld.global.acquire.gpu.u32 %0, [%1];"
                                 : "=r"(v) : "l"(ctr) : "memory");
                    if (v >= tgt) break;
                    if (++spins > 8192) __nanosleep(32);
                } while (true);
            }
            __syncthreads();
        }

        // ---- stage h(t-1) into smem: one float4 per thread (4KB/CTA) ----
        const float* hprev = (t == 0) ? h0 : (ys + (size_t)(t - 1) * H_DIM);
        {
            const float4 hv = __ldcg((const float4*)(hprev + 4 * tid));
            *(float4*)(sh_h + 4 * tid) = hv;
        }
        __syncthreads();

        // ---- dot: 8x LDS.128 + 64 packed FFMA2 per thread ----
        unsigned long long acc[4][2] = {};
#pragma unroll
        for (int k4 = 0; k4 < 8; k4++) {
            const float4 hv = *(const float4*)(sh_h + 4 * l + 128 * k4);
            const unsigned long long h01 = pk2(hv.x, hv.y);
            const unsigned long long h23 = pk2(hv.z, hv.w);
#pragma unroll
            for (int g = 0; g < 4; g++) {
                fma2(acc[g][0], wpk[g][2 * k4 + 0], h01);
                fma2(acc[g][1], wpk[g][2 * k4 + 1], h23);
            }
        }
        float a0 = lo2(acc[0][0]) + hi2(acc[0][0]) + lo2(acc[0][1]) + hi2(acc[0][1]);
        float a1 = lo2(acc[1][0]) + hi2(acc[1][0]) + lo2(acc[1][1]) + hi2(acc[1][1]);
        float a2 = lo2(acc[2][0]) + hi2(acc[2][0]) + lo2(acc[2][1]) + hi2(acc[2][1]);
        float a3 = lo2(acc[3][0]) + hi2(acc[3][0]) + lo2(acc[3][1]) + hi2(acc[3][1]);

#pragma unroll
        for (int off = 16; off > 0; off >>= 1) {
            a0 += __shfl_xor_sync(0xFFFFFFFFu, a0, off);
            a1 += __shfl_xor_sync(0xFFFFFFFFu, a1, off);
            a2 += __shfl_xor_sync(0xFFFFFFFFu, a2, off);
            a3 += __shfl_xor_sync(0xFFFFFFFFu, a3, off);
        }
        // all lanes now hold a0..a3

        // ---- gates: lanes 0..3 compute their activation in parallel ----
        float act = 0.0f;
        if (l < 4) {
            const float pre = (l == 0 ? a0 : l == 1 ? a1 : l == 2 ? a2 : a3) + gxv;
            act = (l == 2) ? tanh_fast(pre) : sigmoid_fast(pre);
        }
        const float i_ = __shfl_sync(0xFFFFFFFFu, act, 0);
        const float f_ = __shfl_sync(0xFFFFFFFFu, act, 1);
        const float g_ = __shfl_sync(0xFFFFFFFFu, act, 2);
        const float o_ = __shfl_sync(0xFFFFFFFFu, act, 3);

        if (l == 0) {
            const float c_ = f_ * creg + i_ * g_;
            const float h_ = o_ * tanh_fast(c_);
            creg = c_;
            __stcg(&ys[(size_t)t * H_DIM + u], h_);
            if (t == T_SEQ - 1) {
                out[OFF_HT + u] = h_;
                out[OFF_CT + u] = c_;
            }
        }

        // ---- all 8 h stores done -> one release per CTA ----
        __syncthreads();
        if (tid == 7 * 32) {
            asm volatile("red.release.gpu.global.add.u32 [%0], %1;"
                         :: "l"(ctr), "r"(1u) : "memory");
        }

        // prefetch gx for step t+1 (off critical path, hidden behind next wait)
        if (l < 4 && t + 1 < T_SEQ) {
            gxv = __ldcg(gx + (size_t)(t + 1) * G4 + l * H_DIM + u);
        }
    }
}

// ---------------- policy head: action_mean + log_std broadcast ----------------
__global__ __launch_bounds__(128) void head_kernel(
    const float* __restrict__ mean_w, const float* __restrict__ mean_b,
    const float* __restrict__ log_std, const float* __restrict__ h2,
    float* __restrict__ out)
{
    const int t = blockIdx.x;
    const int w = threadIdx.x >> 5;
    const int l = threadIdx.x & 31;
    const float* hrow = h2 + (size_t)t * H_DIM;
    const float* wrow = mean_w + (size_t)w * H_DIM;
    float s = 0.f;
#pragma unroll
    for (int k = 0; k < H_DIM / 32; k++)
        s = fmaf(hrow[l + 32 * k], wrow[l + 32 * k], s);
#pragma unroll
    for (int off = 16; off > 0; off >>= 1)
        s += __shfl_xor_sync(0xFFFFFFFFu, s, off);
    if (l == 0) {
        out[OFF_MEAN + t * OUT_DIM + w] = s + mean_b[w];
        out[OFF_LSTD + t * OUT_DIM + w] = log_std[w];
    }
}

// ---------------- launch ----------------
extern "C" void kernel_launch(void* const* d_in, const int* in_sizes, int n_in,
                              void* d_out, int out_size)
{
    (void)in_sizes; (void)n_in; (void)out_size;
    const float* x      = (const float*)d_in[0];
    const float* h0     = (const float*)d_in[1];
    const float* c0     = (const float*)d_in[2];
    const float* w_ih   = (const float*)d_in[3];
    const float* w_hh   = (const float*)d_in[4];
    const float* b_ih   = (const float*)d_in[5];
    const float* b_hh   = (const float*)d_in[6];
    const float* fc1_w  = (const float*)d_in[7];
    const float* fc1_b  = (const float*)d_in[8];
    const float* fc2_w  = (const float*)d_in[9];
    const float* fc2_b  = (const float*)d_in[10];
    const float* mean_w = (const float*)d_in[11];
    const float* mean_b = (const float*)d_in[12];
    const float* lstd   = (const float*)d_in[13];
    float* out = (float*)d_out;

    float *gx, *ys, *h1, *h2;
    cudaGetSymbolAddress((void**)&gx, g_gx);
    cudaGetSymbolAddress((void**)&ys, g_ys);
    cudaGetSymbolAddress((void**)&h1, g_h1);
    cudaGetSymbolAddress((void**)&h2, g_h2);

    reset_kernel<<<1, 32>>>();

    // gx = x @ w_ih.T + b_ih + b_hh   [2048, 4096]
    gemm_nt_kernel<<<dim3(G4 / BN, T_SEQ / BM), 256>>>(
        x, w_ih, b_ih, b_hh, gx, T_SEQ, G4, IN_DIM, 0);

    // sequential LSTM
    lstm_kernel<<<NCTA, 256>>>(w_hh, h0, c0, gx, ys, out);

    // h1 = relu(ys @ fc1_w.T + fc1_b)
    gemm_nt_kernel<<<dim3(H_DIM / BN, T_SEQ / BM), 256>>>(
        ys, fc1_w, fc1_b, nullptr, h1, T_SEQ, H_DIM, H_DIM, 1);

    // h2 = relu(h1 @ fc2_w.T + fc2_b)
    gemm_nt_kernel<<<dim3(H_DIM / BN, T_SEQ / BM), 256>>>(
        h1, fc2_w, fc2_b, nullptr, h2, T_SEQ, H_DIM, H_DIM, 1);

    // action_mean / log_std
    head_kernel<<<T_SEQ, 128>>>(mean_w, mean_b, lstd, h2, out);
}

// round 13
// speedup vs baseline: 1.5453x; 1.5453x over previous
#include <cuda_runtime.h>
#include <math.h>

#define T_SEQ 2048
#define H_DIM 1024
#define IN_DIM 512
#define G4 4096
#define OUT_DIM 4
#define NCTA 128
#define SLICE 8            // hidden units per CTA (one per warp)

#define OFF_MEAN 0
#define OFF_LSTD (T_SEQ * OUT_DIM)
#define OFF_HT   (2 * T_SEQ * OUT_DIM)
#define OFF_CT   (2 * T_SEQ * OUT_DIM + H_DIM)

// ---------------- scratch (static device memory: no allocation) ----------------
__device__ float g_gx[T_SEQ * G4];     // 32 MB: x @ w_ih.T + b_ih + b_hh
__device__ float g_ys[T_SEQ * H_DIM];  // 8 MB: h trace (hot exchange + fc1 input)
__device__ float g_h1[T_SEQ * H_DIM];
__device__ float g_h2[T_SEQ * H_DIM];
__device__ unsigned g_ctr;             // single step counter (RED target)

__global__ void reset_kernel() {
    if (threadIdx.x == 0) g_ctr = 0u;
}

// ---------------- packed f32x2 helpers ----------------
__device__ __forceinline__ unsigned long long pk2(float a, float b) {
    unsigned long long r;
    asm("mov.b64 %0, {%1, %2};" : "=l"(r) : "f"(a), "f"(b));
    return r;
}
__device__ __forceinline__ void fma2(unsigned long long& d,
                                     unsigned long long a, unsigned long long b) {
    asm("fma.rn.f32x2 %0, %1, %2, %0;" : "+l"(d) : "l"(a), "l"(b));
}
__device__ __forceinline__ float lo2(unsigned long long v) {
    return __uint_as_float((unsigned)v);
}
__device__ __forceinline__ float hi2(unsigned long long v) {
    return __uint_as_float((unsigned)(v >> 32));
}
__device__ __forceinline__ float tanh_fast(float x) {
    float r;
    asm("tanh.approx.f32 %0, %1;" : "=f"(r) : "f"(x));
    return r;
}
// sigmoid(x) = 0.5 + 0.5*tanh(x/2): single MUFU instead of exp+rcp chain
__device__ __forceinline__ float sigmoid_fast(float x) {
    return fmaf(tanh_fast(0.5f * x), 0.5f, 0.5f);
}

// ---------------- tiled GEMM: C[M,N] = A[M,K] @ B[N,K]^T + b1 (+b2), opt relu ----
#define BM 64
#define BN 64
#define BK 16

__global__ __launch_bounds__(256) void gemm_nt_kernel(
    const float* __restrict__ A, const float* __restrict__ B,
    const float* __restrict__ b1, const float* __restrict__ b2,
    float* __restrict__ C, int M, int N, int K, int relu)
{
    __shared__ float As[BK][BM + 4];
    __shared__ float Bs[BK][BN + 4];

    const int bm = blockIdx.y * BM;
    const int bn = blockIdx.x * BN;
    const int tid = threadIdx.x;
    const int tx = tid & 15;
    const int ty = tid >> 4;

    const int lr = tid >> 2;
    const int lk = (tid & 3) * 4;

    unsigned long long acc2[4][2] = {};

    for (int k0 = 0; k0 < K; k0 += BK) {
        float4 av = *(const float4*)(A + (size_t)(bm + lr) * K + k0 + lk);
        float4 bv = *(const float4*)(B + (size_t)(bn + lr) * K + k0 + lk);
        __syncthreads();
        As[lk + 0][lr] = av.x; As[lk + 1][lr] = av.y;
        As[lk + 2][lr] = av.z; As[lk + 3][lr] = av.w;
        Bs[lk + 0][lr] = bv.x; Bs[lk + 1][lr] = bv.y;
        Bs[lk + 2][lr] = bv.z; Bs[lk + 3][lr] = bv.w;
        __syncthreads();

#pragma unroll
        for (int kk = 0; kk < BK; kk++) {
            const float4 a4 = *(const float4*)&As[kk][ty * 4];
            const float4 b4 = *(const float4*)&Bs[kk][tx * 4];
            const unsigned long long b01 = pk2(b4.x, b4.y);
            const unsigned long long b23 = pk2(b4.z, b4.w);
            const float a_[4] = {a4.x, a4.y, a4.z, a4.w};
#pragma unroll
            for (int i = 0; i < 4; i++) {
                const unsigned long long aii = pk2(a_[i], a_[i]);
                fma2(acc2[i][0], aii, b01);
                fma2(acc2[i][1], aii, b23);
            }
        }
    }

#pragma unroll
    for (int i = 0; i < 4; i++) {
        const int m = bm + ty * 4 + i;
        float cj[4] = {lo2(acc2[i][0]), hi2(acc2[i][0]),
                       lo2(acc2[i][1]), hi2(acc2[i][1])};
#pragma unroll
        for (int j = 0; j < 4; j++) {
            const int n = bn + tx * 4 + j;
            float v = cj[j] + b1[n];
            if (b2) v += b2[n];
            if (relu) v = fmaxf(v, 0.0f);
            C[(size_t)m * N + n] = v;
        }
    }
}

// ---------------- persistent LSTM recurrence ----------------
// 128 CTAs x 256 threads (8 warps). Warp w owns unit u = cta*8 + w (4 gate rows
// register-resident, f32x2). h(t-1) read by direct LDG.128, ALL 8 loads hoisted
// ahead of the FMA block (MLP=8). Gates on lane 0 with tanh-only activations.
// Sync: single counter, release-RED by warp 7 lane 0, single acquire-poller.
__global__ __launch_bounds__(256, 1) void lstm_kernel(
    const float* __restrict__ w_hh,
    const float* __restrict__ h0, const float* __restrict__ c0,
    const float* __restrict__ gx,
    float* __restrict__ ys,
    float* __restrict__ out)
{
    const int cta = blockIdx.x;
    const int hs = cta * SLICE;
    const int tid = threadIdx.x;
    const int w = tid >> 5;              // warp 0..7; owns unit hs+w
    const int l = tid & 31;
    const int u = hs + w;                // this warp's hidden unit

    // Persistent weights: 4 gate rows of unit u, packed f32x2.
    // Thread covers cols {4l+128*k4 + j}, j=0..3, k4=0..7.
    unsigned long long wpk[4][16];
#pragma unroll
    for (int g = 0; g < 4; g++) {
        const float* wrow = w_hh + (size_t)(g * H_DIM + u) * H_DIM;
#pragma unroll
        for (int k4 = 0; k4 < 8; k4++) {
            const int base = 4 * l + 128 * k4;
            wpk[g][2 * k4 + 0] = pk2(wrow[base + 0], wrow[base + 1]);
            wpk[g][2 * k4 + 1] = pk2(wrow[base + 2], wrow[base + 3]);
        }
    }

    // c state: lane 0 of each warp
    float creg = (l == 0) ? c0[u] : 0.0f;

    // gx prefetch for step 0: lane 0 holds the 4 gate inputs of unit u
    float gxi = 0.f, gxf = 0.f, gxg = 0.f, gxo = 0.f;
    if (l == 0) {
        gxi = __ldcg(gx + 0 * H_DIM + u);
        gxf = __ldcg(gx + 1 * H_DIM + u);
        gxg = __ldcg(gx + 2 * H_DIM + u);
        gxo = __ldcg(gx + 3 * H_DIM + u);
    }

    unsigned* ctr = &g_ctr;

    for (int t = 0; t < T_SEQ; t++) {
        // ---- wait for h(t-1): single poller (warp 7 lane 0) ----
        if (t > 0) {
            if (tid == 7 * 32) {
                const unsigned tgt = (unsigned)(NCTA * t);
                unsigned v;
                int spins = 0;
                do {
                    asm volatile("ld.global.acquire.gpu.u32 %0, [%1];"
                                 : "=r"(v) : "l"(ctr) : "memory");
                    if (v >= tgt) break;
                    if (++spins > 8192) __nanosleep(32);
                } while (true);
            }
            __syncthreads();
        }

        const float* hprev = (t == 0) ? h0 : (ys + (size_t)(t - 1) * H_DIM);

        // ---- hoist ALL 8 h loads (front-batched, MLP=8) ----
        float4 hv[8];
#pragma unroll
        for (int k4 = 0; k4 < 8; k4++)
            hv[k4] = *(const float4*)(hprev + 4 * l + 128 * k4);

        // ---- dot: 64 packed FFMA2 per thread ----
        unsigned long long acc[4][2] = {};
#pragma unroll
        for (int k4 = 0; k4 < 8; k4++) {
            const unsigned long long h01 = pk2(hv[k4].x, hv[k4].y);
            const unsigned long long h23 = pk2(hv[k4].z, hv[k4].w);
#pragma unroll
            for (int g = 0; g < 4; g++) {
                fma2(acc[g][0], wpk[g][2 * k4 + 0], h01);
                fma2(acc[g][1], wpk[g][2 * k4 + 1], h23);
            }
        }
        float a0 = lo2(acc[0][0]) + hi2(acc[0][0]) + lo2(acc[0][1]) + hi2(acc[0][1]);
        float a1 = lo2(acc[1][0]) + hi2(acc[1][0]) + lo2(acc[1][1]) + hi2(acc[1][1]);
        float a2 = lo2(acc[2][0]) + hi2(acc[2][0]) + lo2(acc[2][1]) + hi2(acc[2][1]);
        float a3 = lo2(acc[3][0]) + hi2(acc[3][0]) + lo2(acc[3][1]) + hi2(acc[3][1]);

#pragma unroll
        for (int off = 16; off > 0; off >>= 1) {
            a0 += __shfl_xor_sync(0xFFFFFFFFu, a0, off);
            a1 += __shfl_xor_sync(0xFFFFFFFFu, a1, off);
            a2 += __shfl_xor_sync(0xFFFFFFFFu, a2, off);
            a3 += __shfl_xor_sync(0xFFFFFFFFu, a3, off);
        }

        // ---- gates + h store: lane 0 of each warp, warp-parallel ----
        if (l == 0) {
            const float gi = a0 + gxi;
            const float gf = a1 + gxf;
            const float gg = a2 + gxg;
            const float go = a3 + gxo;
            const float i_ = sigmoid_fast(gi);
            const float f_ = sigmoid_fast(gf);
            const float g_ = tanh_fast(gg);
            const float o_ = sigmoid_fast(go);
            const float c_ = f_ * creg + i_ * g_;
            const float h_ = o_ * tanh_fast(c_);
            creg = c_;
            __stcg(&ys[(size_t)t * H_DIM + u], h_);
            if (t == T_SEQ - 1) {
                out[OFF_HT + u] = h_;
                out[OFF_CT + u] = c_;
            }
        }

        // ---- all 8 h stores done -> one release per CTA ----
        __syncthreads();
        if (tid == 7 * 32) {
            asm volatile("red.release.gpu.global.add.u32 [%0], %1;"
                         :: "l"(ctr), "r"(1u) : "memory");
        }

        // prefetch gx for step t+1 (off critical path, hidden behind next wait)
        if (l == 0 && t + 1 < T_SEQ) {
            const float* gxt = gx + (size_t)(t + 1) * G4 + u;
            gxi = __ldcg(gxt + 0 * H_DIM);
            gxf = __ldcg(gxt + 1 * H_DIM);
            gxg = __ldcg(gxt + 2 * H_DIM);
            gxo = __ldcg(gxt + 3 * H_DIM);
        }
    }
}

// ---------------- policy head: action_mean + log_std broadcast ----------------
__global__ __launch_bounds__(128) void head_kernel(
    const float* __restrict__ mean_w, const float* __restrict__ mean_b,
    const float* __restrict__ log_std, const float* __restrict__ h2,
    float* __restrict__ out)
{
    const int t = blockIdx.x;
    const int w = threadIdx.x >> 5;
    const int l = threadIdx.x & 31;
    const float* hrow = h2 + (size_t)t * H_DIM;
    const float* wrow = mean_w + (size_t)w * H_DIM;
    float s = 0.f;
#pragma unroll
    for (int k = 0; k < H_DIM / 32; k++)
        s = fmaf(hrow[l + 32 * k], wrow[l + 32 * k], s);
#pragma unroll
    for (int off = 16; off > 0; off >>= 1)
        s += __shfl_xor_sync(0xFFFFFFFFu, s, off);
    if (l == 0) {
        out[OFF_MEAN + t * OUT_DIM + w] = s + mean_b[w];
        out[OFF_LSTD + t * OUT_DIM + w] = log_std[w];
    }
}

// ---------------- launch ----------------
extern "C" void kernel_launch(void* const* d_in, const int* in_sizes, int n_in,
                              void* d_out, int out_size)
{
    (void)in_sizes; (void)n_in; (void)out_size;
    const float* x      = (const float*)d_in[0];
    const float* h0     = (const float*)d_in[1];
    const float* c0     = (const float*)d_in[2];
    const float* w_ih   = (const float*)d_in[3];
    const float* w_hh   = (const float*)d_in[4];
    const float* b_ih   = (const float*)d_in[5];
    const float* b_hh   = (const float*)d_in[6];
    const float* fc1_w  = (const float*)d_in[7];
    const float* fc1_b  = (const float*)d_in[8];
    const float* fc2_w  = (const float*)d_in[9];
    const float* fc2_b  = (const float*)d_in[10];
    const float* mean_w = (const float*)d_in[11];
    const float* mean_b = (const float*)d_in[12];
    const float* lstd   = (const float*)d_in[13];
    float* out = (float*)d_out;

    float *gx, *ys, *h1, *h2;
    cudaGetSymbolAddress((void**)&gx, g_gx);
    cudaGetSymbolAddress((void**)&ys, g_ys);
    cudaGetSymbolAddress((void**)&h1, g_h1);
    cudaGetSymbolAddress((void**)&h2, g_h2);

    reset_kernel<<<1, 32>>>();

    // gx = x @ w_ih.T + b_ih + b_hh   [2048, 4096]
    gemm_nt_kernel<<<dim3(G4 / BN, T_SEQ / BM), 256>>>(
        x, w_ih, b_ih, b_hh, gx, T_SEQ, G4, IN_DIM, 0);

    // sequential LSTM
    lstm_kernel<<<NCTA, 256>>>(w_hh, h0, c0, gx, ys, out);

    // h1 = relu(ys @ fc1_w.T + fc1_b)
    gemm_nt_kernel<<<dim3(H_DIM / BN, T_SEQ / BM), 256>>>(
        ys, fc1_w, fc1_b, nullptr, h1, T_SEQ, H_DIM, H_DIM, 1);

    // h2 = relu(h1 @ fc2_w.T + fc2_b)
    gemm_nt_kernel<<<dim3(H_DIM / BN, T_SEQ / BM), 256>>>(
        h1, fc2_w, fc2_b, nullptr, h2, T_SEQ, H_DIM, H_DIM, 1);

    // action_mean / log_std
    head_kernel<<<T_SEQ, 128>>>(mean_w, mean_b, lstd, h2, out);
}

// round 14
// speedup vs baseline: 1.5778x; 1.0210x over previous
#include <cuda_runtime.h>
#include <math.h>

#define T_SEQ 2048
#define H_DIM 1024
#define IN_DIM 512
#define G4 4096
#define OUT_DIM 4
#define NCTA 128
#define SLICE 8            // hidden units per CTA (one per warp)

#define OFF_MEAN 0
#define OFF_LSTD (T_SEQ * OUT_DIM)
#define OFF_HT   (2 * T_SEQ * OUT_DIM)
#define OFF_CT   (2 * T_SEQ * OUT_DIM + H_DIM)

// ---------------- scratch (static device memory: no allocation) ----------------
__device__ float g_gx[T_SEQ * G4];     // 32 MB: x @ w_ih.T + b_ih + b_hh
__device__ float g_ys[T_SEQ * H_DIM];  // 8 MB: h trace (hot exchange + fc1 input)
__device__ float g_h1[T_SEQ * H_DIM];
__device__ float g_h2[T_SEQ * H_DIM];
__device__ unsigned g_ctr;             // single step counter (RED target)

__global__ void reset_kernel() {
    if (threadIdx.x == 0) g_ctr = 0u;
}

// ---------------- packed f32x2 helpers ----------------
__device__ __forceinline__ unsigned long long pk2(float a, float b) {
    unsigned long long r;
    asm("mov.b64 %0, {%1, %2};" : "=l"(r) : "f"(a), "f"(b));
    return r;
}
__device__ __forceinline__ void fma2(unsigned long long& d,
                                     unsigned long long a, unsigned long long b) {
    asm("fma.rn.f32x2 %0, %1, %2, %0;" : "+l"(d) : "l"(a), "l"(b));
}
__device__ __forceinline__ float lo2(unsigned long long v) {
    return __uint_as_float((unsigned)v);
}
__device__ __forceinline__ float hi2(unsigned long long v) {
    return __uint_as_float((unsigned)(v >> 32));
}
__device__ __forceinline__ float tanh_fast(float x) {
    float r;
    asm("tanh.approx.f32 %0, %1;" : "=f"(r) : "f"(x));
    return r;
}
// sigmoid(x) = 0.5 + 0.5*tanh(x/2): single MUFU instead of exp+rcp chain
__device__ __forceinline__ float sigmoid_fast(float x) {
    return fmaf(tanh_fast(0.5f * x), 0.5f, 0.5f);
}

// ---------------- tiled GEMM: C[M,N] = A[M,K] @ B[N,K]^T + b1 (+b2), opt relu ----
#define BM 64
#define BN 64
#define BK 16

__global__ __launch_bounds__(256) void gemm_nt_kernel(
    const float* __restrict__ A, const float* __restrict__ B,
    const float* __restrict__ b1, const float* __restrict__ b2,
    float* __restrict__ C, int M, int N, int K, int relu)
{
    __shared__ float As[BK][BM + 4];
    __shared__ float Bs[BK][BN + 4];

    const int bm = blockIdx.y * BM;
    const int bn = blockIdx.x * BN;
    const int tid = threadIdx.x;
    const int tx = tid & 15;
    const int ty = tid >> 4;

    const int lr = tid >> 2;
    const int lk = (tid & 3) * 4;

    unsigned long long acc2[4][2] = {};

    for (int k0 = 0; k0 < K; k0 += BK) {
        float4 av = *(const float4*)(A + (size_t)(bm + lr) * K + k0 + lk);
        float4 bv = *(const float4*)(B + (size_t)(bn + lr) * K + k0 + lk);
        __syncthreads();
        As[lk + 0][lr] = av.x; As[lk + 1][lr] = av.y;
        As[lk + 2][lr] = av.z; As[lk + 3][lr] = av.w;
        Bs[lk + 0][lr] = bv.x; Bs[lk + 1][lr] = bv.y;
        Bs[lk + 2][lr] = bv.z; Bs[lk + 3][lr] = bv.w;
        __syncthreads();

#pragma unroll
        for (int kk = 0; kk < BK; kk++) {
            const float4 a4 = *(const float4*)&As[kk][ty * 4];
            const float4 b4 = *(const float4*)&Bs[kk][tx * 4];
            const unsigned long long b01 = pk2(b4.x, b4.y);
            const unsigned long long b23 = pk2(b4.z, b4.w);
            const float a_[4] = {a4.x, a4.y, a4.z, a4.w};
#pragma unroll
            for (int i = 0; i < 4; i++) {
                const unsigned long long aii = pk2(a_[i], a_[i]);
                fma2(acc2[i][0], aii, b01);
                fma2(acc2[i][1], aii, b23);
            }
        }
    }

#pragma unroll
    for (int i = 0; i < 4; i++) {
        const int m = bm + ty * 4 + i;
        float cj[4] = {lo2(acc2[i][0]), hi2(acc2[i][0]),
                       lo2(acc2[i][1]), hi2(acc2[i][1])};
#pragma unroll
        for (int j = 0; j < 4; j++) {
            const int n = bn + tx * 4 + j;
            float v = cj[j] + b1[n];
            if (b2) v += b2[n];
            if (relu) v = fmaxf(v, 0.0f);
            C[(size_t)m * N + n] = v;
        }
    }
}

// ---------------- persistent LSTM recurrence ----------------
// 128 CTAs x 256 threads (8 warps). Warp w owns unit u = cta*8 + w (4 gate rows
// register-resident, f32x2). h(t-1) staged ONCE per CTA into smem (1 float4 per
// thread = 4KB; 8x less L2 traffic than per-warp global reads), then the dot
// reads hoisted LDS.128. Gates on lane 0, tanh-only activations.
// Sync: single counter, release-RED by warp 7 lane 0, single acquire-poller.
__global__ __launch_bounds__(256, 1) void lstm_kernel(
    const float* __restrict__ w_hh,
    const float* __restrict__ h0, const float* __restrict__ c0,
    const float* __restrict__ gx,
    float* __restrict__ ys,
    float* __restrict__ out)
{
    const int cta = blockIdx.x;
    const int hs = cta * SLICE;
    const int tid = threadIdx.x;
    const int w = tid >> 5;              // warp 0..7; owns unit hs+w
    const int l = tid & 31;
    const int u = hs + w;                // this warp's hidden unit

    // Persistent weights: 4 gate rows of unit u, packed f32x2.
    // Thread covers cols {4l+128*k4 + j}, j=0..3, k4=0..7.
    unsigned long long wpk[4][16];
#pragma unroll
    for (int g = 0; g < 4; g++) {
        const float* wrow = w_hh + (size_t)(g * H_DIM + u) * H_DIM;
#pragma unroll
        for (int k4 = 0; k4 < 8; k4++) {
            const int base = 4 * l + 128 * k4;
            wpk[g][2 * k4 + 0] = pk2(wrow[base + 0], wrow[base + 1]);
            wpk[g][2 * k4 + 1] = pk2(wrow[base + 2], wrow[base + 3]);
        }
    }

    __shared__ float sh_h[H_DIM];

    // c state: lane 0 of each warp
    float creg = (l == 0) ? c0[u] : 0.0f;

    // gx prefetch for step 0: lane 0 holds the 4 gate inputs of unit u
    float gxi = 0.f, gxf = 0.f, gxg = 0.f, gxo = 0.f;
    if (l == 0) {
        gxi = __ldcg(gx + 0 * H_DIM + u);
        gxf = __ldcg(gx + 1 * H_DIM + u);
        gxg = __ldcg(gx + 2 * H_DIM + u);
        gxo = __ldcg(gx + 3 * H_DIM + u);
    }

    unsigned* ctr = &g_ctr;

    for (int t = 0; t < T_SEQ; t++) {
        // ---- wait for h(t-1): single poller (warp 7 lane 0) ----
        if (t > 0) {
            if (tid == 7 * 32) {
                const unsigned tgt = (unsigned)(NCTA * t);
                unsigned v;
                int spins = 0;
                do {
                    asm volatile("ld.global.acquire.gpu.u32 %0, [%1];"
                                 : "=r"(v) : "l"(ctr) : "memory");
                    if (v >= tgt) break;
                    if (++spins > 8192) __nanosleep(32);
                } while (true);
            }
            __syncthreads();
        }

        // ---- stage h(t-1) into smem once per CTA (4KB, warp-contiguous) ----
        const float* hprev = (t == 0) ? h0 : (ys + (size_t)(t - 1) * H_DIM);
        {
            const float4 hv4 = __ldcg((const float4*)(hprev + 4 * tid));
            *(float4*)(sh_h + 4 * tid) = hv4;
        }
        __syncthreads();

        // ---- hoist all 8 h chunks from smem (LDS.128, 29-cyc) ----
        float4 hv[8];
#pragma unroll
        for (int k4 = 0; k4 < 8; k4++)
            hv[k4] = *(const float4*)(sh_h + 4 * l + 128 * k4);

        // ---- dot: 64 packed FFMA2 per thread ----
        unsigned long long acc[4][2] = {};
#pragma unroll
        for (int k4 = 0; k4 < 8; k4++) {
            const unsigned long long h01 = pk2(hv[k4].x, hv[k4].y);
            const unsigned long long h23 = pk2(hv[k4].z, hv[k4].w);
#pragma unroll
            for (int g = 0; g < 4; g++) {
                fma2(acc[g][0], wpk[g][2 * k4 + 0], h01);
                fma2(acc[g][1], wpk[g][2 * k4 + 1], h23);
            }
        }
        float a0 = lo2(acc[0][0]) + hi2(acc[0][0]) + lo2(acc[0][1]) + hi2(acc[0][1]);
        float a1 = lo2(acc[1][0]) + hi2(acc[1][0]) + lo2(acc[1][1]) + hi2(acc[1][1]);
        float a2 = lo2(acc[2][0]) + hi2(acc[2][0]) + lo2(acc[2][1]) + hi2(acc[2][1]);
        float a3 = lo2(acc[3][0]) + hi2(acc[3][0]) + lo2(acc[3][1]) + hi2(acc[3][1]);

#pragma unroll
        for (int off = 16; off > 0; off >>= 1) {
            a0 += __shfl_xor_sync(0xFFFFFFFFu, a0, off);
            a1 += __shfl_xor_sync(0xFFFFFFFFu, a1, off);
            a2 += __shfl_xor_sync(0xFFFFFFFFu, a2, off);
            a3 += __shfl_xor_sync(0xFFFFFFFFu, a3, off);
        }

        // ---- gates + h store: lane 0 of each warp, warp-parallel ----
        if (l == 0) {
            const float gi = a0 + gxi;
            const float gf = a1 + gxf;
            const float gg = a2 + gxg;
            const float go = a3 + gxo;
            const float i_ = sigmoid_fast(gi);
            const float f_ = sigmoid_fast(gf);
            const float g_ = tanh_fast(gg);
            const float o_ = sigmoid_fast(go);
            const float c_ = f_ * creg + i_ * g_;
            const float h_ = o_ * tanh_fast(c_);
            creg = c_;
            __stcg(&ys[(size_t)t * H_DIM + u], h_);
            if (t == T_SEQ - 1) {
                out[OFF_HT + u] = h_;
                out[OFF_CT + u] = c_;
            }
        }

        // ---- all 8 h stores done -> one release per CTA ----
        __syncthreads();
        if (tid == 7 * 32) {
            asm volatile("red.release.gpu.global.add.u32 [%0], %1;"
                         :: "l"(ctr), "r"(1u) : "memory");
        }

        // prefetch gx for step t+1 (off critical path, hidden behind next wait)
        if (l == 0 && t + 1 < T_SEQ) {
            const float* gxt = gx + (size_t)(t + 1) * G4 + u;
            gxi = __ldcg(gxt + 0 * H_DIM);
            gxf = __ldcg(gxt + 1 * H_DIM);
            gxg = __ldcg(gxt + 2 * H_DIM);
            gxo = __ldcg(gxt + 3 * H_DIM);
        }
    }
}

// ---------------- policy head: action_mean + log_std broadcast ----------------
__global__ __launch_bounds__(128) void head_kernel(
    const float* __restrict__ mean_w, const float* __restrict__ mean_b,
    const float* __restrict__ log_std, const float* __restrict__ h2,
    float* __restrict__ out)
{
    const int t = blockIdx.x;
    const int w = threadIdx.x >> 5;
    const int l = threadIdx.x & 31;
    const float* hrow = h2 + (size_t)t * H_DIM;
    const float* wrow = mean_w + (size_t)w * H_DIM;
    float s = 0.f;
#pragma unroll
    for (int k = 0; k < H_DIM / 32; k++)
        s = fmaf(hrow[l + 32 * k], wrow[l + 32 * k], s);
#pragma unroll
    for (int off = 16; off > 0; off >>= 1)
        s += __shfl_xor_sync(0xFFFFFFFFu, s, off);
    if (l == 0) {
        out[OFF_MEAN + t * OUT_DIM + w] = s + mean_b[w];
        out[OFF_LSTD + t * OUT_DIM + w] = log_std[w];
    }
}

// ---------------- launch ----------------
extern "C" void kernel_launch(void* const* d_in, const int* in_sizes, int n_in,
                              void* d_out, int out_size)
{
    (void)in_sizes; (void)n_in; (void)out_size;
    const float* x      = (const float*)d_in[0];
    const float* h0     = (const float*)d_in[1];
    const float* c0     = (const float*)d_in[2];
    const float* w_ih   = (const float*)d_in[3];
    const float* w_hh   = (const float*)d_in[4];
    const float* b_ih   = (const float*)d_in[5];
    const float* b_hh   = (const float*)d_in[6];
    const float* fc1_w  = (const float*)d_in[7];
    const float* fc1_b  = (const float*)d_in[8];
    const float* fc2_w  = (const float*)d_in[9];
    const float* fc2_b  = (const float*)d_in[10];
    const float* mean_w = (const float*)d_in[11];
    const float* mean_b = (const float*)d_in[12];
    const float* lstd   = (const float*)d_in[13];
    float* out = (float*)d_out;

    float *gx, *ys, *h1, *h2;
    cudaGetSymbolAddress((void**)&gx, g_gx);
    cudaGetSymbolAddress((void**)&ys, g_ys);
    cudaGetSymbolAddress((void**)&h1, g_h1);
    cudaGetSymbolAddress((void**)&h2, g_h2);

    reset_kernel<<<1, 32>>>();

    // gx = x @ w_ih.T + b_ih + b_hh   [2048, 4096]
    gemm_nt_kernel<<<dim3(G4 / BN, T_SEQ / BM), 256>>>(
        x, w_ih, b_ih, b_hh, gx, T_SEQ, G4, IN_DIM, 0);

    // sequential LSTM
    lstm_kernel<<<NCTA, 256>>>(w_hh, h0, c0, gx, ys, out);

    // h1 = relu(ys @ fc1_w.T + fc1_b)
    gemm_nt_kernel<<<dim3(H_DIM / BN, T_SEQ / BM), 256>>>(
        ys, fc1_w, fc1_b, nullptr, h1, T_SEQ, H_DIM, H_DIM, 1);

    // h2 = relu(h1 @ fc2_w.T + fc2_b)
    gemm_nt_kernel<<<dim3(H_DIM / BN, T_SEQ / BM), 256>>>(
        h1, fc2_w, fc2_b, nullptr, h2, T_SEQ, H_DIM, H_DIM, 1);

    // action_mean / log_std
    head_kernel<<<T_SEQ, 128>>>(mean_w, mean_b, lstd, h2, out);
}